// round 15
// baseline (speedup 1.0000x reference)
#include <cuda_runtime.h>
#include <cuda_fp16.h>
#include <cstdint>
#include <math.h>

// phi (64,256) row-major, X (256,K), Y (64,K); k = idx+1 active columns.
constexpr int NROW = 256;
constexpr int MDIM = 64;
constexpr int NT   = 64;    // columns per CTA tile
constexpr int TPB  = 256;   // 8 warps; 5 CTAs/SM

// ---- SMEM map (fp16 operands) ----
constexpr int PHA = 0;        // phi [64][264] fp16 row-major (k-contig), 528B stride
constexpr int XF  = 33792;    // X quarter-tile [64 cols][64 k] fp16, 144B stride (9.2KB)
constexpr int RS  = 33792;    // resid [64 cols][72] fp16, 144B stride; aliases XF exactly
constexpr int SMEM_TOTAL = 33792 + 9216 + 128;   // 43136 -> 5 CTAs/SM

constexpr int PHA_SB = 528;
constexpr int XF_SB  = 144;   // 9 x 16B -> STS.128 & ldmatrix conflict-free (9 coprime 8)
constexpr int RS_SB  = 144;

__device__ __forceinline__ uint32_t smem_u32(const void* p) {
    uint32_t a;
    asm("{ .reg .u64 t; cvta.to.shared.u64 t, %1; cvt.u32.u64 %0, t; }" : "=r"(a) : "l"(p));
    return a;
}
__device__ __forceinline__ uint32_t pack_h2(float a, float b) {
    __half ha = __float2half_rn(a), hb = __float2half_rn(b);
    return (uint32_t)__half_as_ushort(ha) | ((uint32_t)__half_as_ushort(hb) << 16);
}

#define MMA_F16(c, a, b0, b1)                                                   \
    asm volatile("mma.sync.aligned.m16n8k16.row.col.f32.f16.f16.f32 "           \
        "{%0,%1,%2,%3}, {%4,%5,%6,%7}, {%8,%9}, {%0,%1,%2,%3};"                 \
        : "+f"((c)[0]), "+f"((c)[1]), "+f"((c)[2]), "+f"((c)[3])                \
        : "r"((a)[0]), "r"((a)[1]), "r"((a)[2]), "r"((a)[3]), "r"(b0), "r"(b1))

#define LDMX4(r, addr)                                                          \
    asm volatile("ldmatrix.sync.aligned.m8n8.x4.shared.b16 {%0,%1,%2,%3}, [%4];"\
        : "=r"((r)[0]), "=r"((r)[1]), "=r"((r)[2]), "=r"((r)[3]) : "r"(addr))
#define LDMX4T(r, addr)                                                         \
    asm volatile("ldmatrix.sync.aligned.m8n8.x4.trans.shared.b16 {%0,%1,%2,%3}, [%4];" \
        : "=r"((r)[0]), "=r"((r)[1]), "=r"((r)[2]), "=r"((r)[3]) : "r"(addr))
#define LDMX2(r, addr)                                                          \
    asm volatile("ldmatrix.sync.aligned.m8n8.x2.shared.b16 {%0,%1}, [%2];"      \
        : "=r"((r)[0]), "=r"((r)[1]) : "r"(addr))

extern __shared__ char smem_g[];

__global__ __launch_bounds__(TPB, 5)
void ista_hmma_kernel(const float* __restrict__ phi,
                      const float* __restrict__ X,
                      const float* __restrict__ Y,
                      const float* __restrict__ step,
                      const int*   __restrict__ idxp,
                      float*       __restrict__ outX,
                      int K)
{
    char* smem = smem_g;
    const int tid  = threadIdx.x;
    const int w    = tid >> 5;
    const int lane = tid & 31;
    const int g    = lane >> 2;
    const int tg   = lane & 3;
    const int base = blockIdx.x * NT;
    const int kact = *idxp + 1;

    // ---------------- passthrough tiles ----------------
    if (base >= kact) {
        const int col = base + (tid & 63);
        if (col < K) {
            for (int n = (tid >> 6); n < NROW; n += 4)
                outX[(size_t)n * K + col] = X[(size_t)n * K + col];
        }
        return;
    }

    const float s = *step;

    uint32_t* pha16u = (uint32_t*)(smem + PHA);
    uint16_t* rs16   = (uint16_t*)(smem + RS);

    const uint32_t pha_b = smem_u32(smem + PHA);
    const uint32_t xf_b  = smem_u32(smem + XF);
    const uint32_t rs_b  = smem_u32(smem + RS);

    // ---------------- stage phi (fp16, native row-major) ----------------
    for (int it = tid; it < MDIM * 128; it += TPB) {
        const int m = it >> 7, kp = it & 127;
        const float2 v = *(const float2*)(phi + m * NROW + 2 * kp);
        pha16u[m * 132 + kp] = pack_h2(v.x, v.y);
    }

    // staging geometry: col = tid&63, k-quarter-of-stage = tid>>6 (16 rows = 2 quads)
    const int scol = tid & 63;
    const int kq   = tid >> 6;
    int gc = base + scol; gc = (gc < K) ? gc : (K - 1);

    // ================= GEMM A: R(64x64) = phi . Xtile, 4 k-stages of 64 =================
    const int mbase = 32 * (w & 1);
    const int nbase = 16 * (w >> 1);
    float cA[2][2][4];
    #pragma unroll
    for (int mt = 0; mt < 2; ++mt)
        #pragma unroll
        for (int nt = 0; nt < 2; ++nt)
            #pragma unroll
            for (int q = 0; q < 4; ++q) cA[mt][nt][q] = 0.0f;

    const uint32_t a_row_off = (uint32_t)(lane & 15) * PHA_SB + (uint32_t)((lane >> 4) << 3) * 2;
    const uint32_t b_row     = (uint32_t)(lane & 7);
    const uint32_t b_koff    = (uint32_t)(((lane >> 3) & 1) << 4);

    #pragma unroll 1
    for (int stage = 0; stage < 4; ++stage) {
        // stage this 64-row k-chunk of X (fp16, STS.128 conflict-free: 9x16B stride)
        #pragma unroll
        for (int q = 0; q < 2; ++q) {
            const int r0 = stage * 64 + kq * 16 + q * 8;
            uint32_t u[4];
            #pragma unroll
            for (int j = 0; j < 4; ++j) {
                const float a = X[(size_t)(r0 + 2 * j) * K + gc];
                const float b = X[(size_t)(r0 + 2 * j + 1) * K + gc];
                u[j] = pack_h2(a, b);
            }
            *(uint4*)(smem + XF + scol * XF_SB + (kq * 2 + q) * 16)
                = make_uint4(u[0], u[1], u[2], u[3]);
        }
        __syncthreads();

        #pragma unroll
        for (int ks = 0; ks < 4; ++ks) {
            const int k0g = stage * 64 + ks * 16;   // phi k (global)
            const int k0l = ks * 16;                // XF k (local to stage)
            uint32_t a[2][4];
            #pragma unroll
            for (int mt = 0; mt < 2; ++mt) {
                const uint32_t aoff = (uint32_t)(mbase + 16 * mt) * PHA_SB
                                    + (uint32_t)k0g * 2 + a_row_off;
                LDMX4(a[mt], pha_b + aoff);
            }
            #pragma unroll
            for (int nt = 0; nt < 2; ++nt) {
                const uint32_t roff = (uint32_t)(nbase + nt * 8 + b_row) * XF_SB
                                    + (uint32_t)k0l * 2 + b_koff;
                uint32_t b[2];
                LDMX2(b, xf_b + roff);
                #pragma unroll
                for (int mt = 0; mt < 2; ++mt)
                    MMA_F16(cA[mt][nt], a[mt], b[0], b[1]);
            }
        }
        __syncthreads();   // buffer consumed before restage / RS alias
    }

    // ---- epilogue A: r = s*(y - R) -> fp16 -> Rs[n][m] (Y read direct) ----
    #pragma unroll
    for (int mt = 0; mt < 2; ++mt)
        #pragma unroll
        for (int nt = 0; nt < 2; ++nt) {
            const int nloc = nbase + nt * 8 + 2 * tg;
            int col0 = base + nloc; col0 = (col0 < K - 1) ? col0 : (K - 2);
            const int m0 = mbase + 16 * mt + g, m1 = m0 + 8;
            const float2 y0 = *(const float2*)(Y + (size_t)m0 * K + col0);
            const float2 y1 = *(const float2*)(Y + (size_t)m1 * K + col0);
            rs16[nloc * 72 + m0]       = __half_as_ushort(__float2half_rn(s * (y0.x - cA[mt][nt][0])));
            rs16[(nloc + 1) * 72 + m0] = __half_as_ushort(__float2half_rn(s * (y0.y - cA[mt][nt][1])));
            rs16[nloc * 72 + m1]       = __half_as_ushort(__float2half_rn(s * (y1.x - cA[mt][nt][2])));
            rs16[(nloc + 1) * 72 + m1] = __half_as_ushort(__float2half_rn(s * (y1.y - cA[mt][nt][3])));
        }
    __syncthreads();

    // ================= GEMM B: corr(256x64) = phiT . R, K=64, 4 passes of n16 =================
    const int lrow = (lane & 7) + ((lane & 16) >> 1);
    const int lcol = (lane & 8);

    #pragma unroll 1
    for (int pass = 0; pass < 4; ++pass) {
        const int nb = pass * 16;
        float cB[2][2][4];
        #pragma unroll
        for (int mt = 0; mt < 2; ++mt)
            #pragma unroll
            for (int nt = 0; nt < 2; ++nt)
                #pragma unroll
                for (int q = 0; q < 4; ++q) cB[mt][nt][q] = 0.0f;

        #pragma unroll
        for (int ks = 0; ks < 4; ++ks) {
            const int k0 = ks * 16;
            uint32_t at[2][4];
            #pragma unroll
            for (int mt = 0; mt < 2; ++mt) {
                const int m0 = 32 * w + 16 * mt;
                const uint32_t off = (uint32_t)((k0 + lrow) * PHA_SB + (m0 + lcol) * 2);
                LDMX4T(at[mt], pha_b + off);
            }
            #pragma unroll
            for (int nt = 0; nt < 2; ++nt) {
                const uint32_t roff = (uint32_t)(nb + nt * 8 + b_row) * RS_SB
                                    + (uint32_t)k0 * 2 + b_koff;
                uint32_t b[2];
                LDMX2(b, rs_b + roff);
                #pragma unroll
                for (int mt = 0; mt < 2; ++mt)
                    MMA_F16(cB[mt][nt], at[mt], b[0], b[1]);
            }
        }

        // ---- epilogue B: out = thresh(X + corr), passthrough beyond kact ----
        #pragma unroll
        for (int mt = 0; mt < 2; ++mt) {
            #pragma unroll
            for (int nt = 0; nt < 2; ++nt) {
                const int col0 = base + nb + nt * 8 + 2 * tg;
                if (col0 + 1 >= K) continue;
                const int r0 = 32 * w + 16 * mt + g;
                const int r1 = r0 + 8;
                const float2 x0 = *(const float2*)(X + (size_t)r0 * K + col0);
                const float2 x1 = *(const float2*)(X + (size_t)r1 * K + col0);
                float u00 = x0.x + cB[mt][nt][0];
                float u01 = x0.y + cB[mt][nt][1];
                float u10 = x1.x + cB[mt][nt][2];
                float u11 = x1.y + cB[mt][nt][3];
                u00 = (fabsf(u00) > 0.1f) ? u00 : 0.0f;
                u01 = (fabsf(u01) > 0.1f) ? u01 : 0.0f;
                u10 = (fabsf(u10) > 0.1f) ? u10 : 0.0f;
                u11 = (fabsf(u11) > 0.1f) ? u11 : 0.0f;
                const bool a0 = (col0 < kact), a1 = (col0 + 1 < kact);
                float2 o0, o1;
                o0.x = a0 ? u00 : x0.x;  o0.y = a1 ? u01 : x0.y;
                o1.x = a0 ? u10 : x1.x;  o1.y = a1 ? u11 : x1.y;
                *(float2*)(outX + (size_t)r0 * K + col0) = o0;
                *(float2*)(outX + (size_t)r1 * K + col0) = o1;
            }
        }
    }
}

extern "C" void kernel_launch(void* const* d_in, const int* in_sizes, int n_in,
                              void* d_out, int out_size)
{
    const float* phi  = (const float*)d_in[0];
    const float* X    = (const float*)d_in[1];
    const float* Y    = (const float*)d_in[2];
    const float* step = (const float*)d_in[3];
    const int*   idx  = (const int*)d_in[4];

    const int phiN = in_sizes[0];
    const int XN   = in_sizes[1];
    const int K    = XN / NROW;

    float* outX = (float*)d_out;
    if (out_size == phiN + XN) {
        cudaMemcpyAsync(d_out, phi, (size_t)phiN * sizeof(float),
                        cudaMemcpyDeviceToDevice, 0);
        outX = (float*)d_out + phiN;
    }

    cudaFuncSetAttribute(ista_hmma_kernel,
                         cudaFuncAttributeMaxDynamicSharedMemorySize, SMEM_TOTAL);

    const int grid = (K + NT - 1) / NT;
    ista_hmma_kernel<<<grid, TPB, SMEM_TOTAL>>>(phi, X, Y, step, idx, outX, K);
}

// round 16
// speedup vs baseline: 1.0747x; 1.0747x over previous
#include <cuda_runtime.h>
#include <cuda_fp16.h>
#include <cstdint>
#include <math.h>

// phi (64,256) row-major, X (256,K), Y (64,K); k = idx+1 active columns.
constexpr int NROW = 256;
constexpr int MDIM = 64;
constexpr int NT   = 64;    // columns per CTA tile
constexpr int TPB  = 256;   // 8 warps; 4 CTAs/SM

// ---- SMEM map (fp16 operands) ----
constexpr int PHA = 0;        // phi [64][264] fp16 row-major (k-contig), 528B stride
constexpr int XF  = 33792;    // X stage [64 cols][64 k] fp16, 144B stride, DOUBLE buffered
constexpr int XFB = 9216;     // bytes per stage buffer
constexpr int RS  = 33792;    // resid [64 cols][72] fp16, 144B stride; aliases XF buf0
constexpr int SMEM_TOTAL = 33792 + 2 * XFB + 128;   // 52352 -> 4 CTAs/SM

constexpr int PHA_SB = 528;
constexpr int XF_SB  = 144;   // 9 x 16B -> STS.128 & ldmatrix conflict-free (9 coprime 8)
constexpr int RS_SB  = 144;

__device__ __forceinline__ uint32_t smem_u32(const void* p) {
    uint32_t a;
    asm("{ .reg .u64 t; cvta.to.shared.u64 t, %1; cvt.u32.u64 %0, t; }" : "=r"(a) : "l"(p));
    return a;
}
__device__ __forceinline__ uint32_t pack_h2(float a, float b) {
    __half ha = __float2half_rn(a), hb = __float2half_rn(b);
    return (uint32_t)__half_as_ushort(ha) | ((uint32_t)__half_as_ushort(hb) << 16);
}

#define MMA_F16(c, a, b0, b1)                                                   \
    asm volatile("mma.sync.aligned.m16n8k16.row.col.f32.f16.f16.f32 "           \
        "{%0,%1,%2,%3}, {%4,%5,%6,%7}, {%8,%9}, {%0,%1,%2,%3};"                 \
        : "+f"((c)[0]), "+f"((c)[1]), "+f"((c)[2]), "+f"((c)[3])                \
        : "r"((a)[0]), "r"((a)[1]), "r"((a)[2]), "r"((a)[3]), "r"(b0), "r"(b1))

#define LDMX4(r, addr)                                                          \
    asm volatile("ldmatrix.sync.aligned.m8n8.x4.shared.b16 {%0,%1,%2,%3}, [%4];"\
        : "=r"((r)[0]), "=r"((r)[1]), "=r"((r)[2]), "=r"((r)[3]) : "r"(addr))
#define LDMX4T(r, addr)                                                         \
    asm volatile("ldmatrix.sync.aligned.m8n8.x4.trans.shared.b16 {%0,%1,%2,%3}, [%4];" \
        : "=r"((r)[0]), "=r"((r)[1]), "=r"((r)[2]), "=r"((r)[3]) : "r"(addr))
#define LDMX2(r, addr)                                                          \
    asm volatile("ldmatrix.sync.aligned.m8n8.x2.shared.b16 {%0,%1}, [%2];"      \
        : "=r"((r)[0]), "=r"((r)[1]) : "r"(addr))

extern __shared__ char smem_g[];

// ---- helpers: compile-time register indexing only ----
__device__ __forceinline__ void ldg_stage(const float* __restrict__ X, int stage,
                                          int kq, int gc, int K, float (&xr)[16]) {
    #pragma unroll
    for (int j = 0; j < 16; ++j)
        xr[j] = X[(size_t)(stage * 64 + kq * 16 + j) * K + gc];
}
__device__ __forceinline__ void sts_stage(char* smem, int bufoff, int scol, int kq,
                                          const float (&xr)[16]) {
    #pragma unroll
    for (int q = 0; q < 2; ++q) {
        uint32_t u[4];
        #pragma unroll
        for (int j = 0; j < 4; ++j)
            u[j] = pack_h2(xr[q * 8 + 2 * j], xr[q * 8 + 2 * j + 1]);
        *(uint4*)(smem + XF + bufoff + scol * XF_SB + (kq * 2 + q) * 16)
            = make_uint4(u[0], u[1], u[2], u[3]);
    }
}

__global__ __launch_bounds__(TPB, 4)
void ista_hmma_kernel(const float* __restrict__ phi,
                      const float* __restrict__ X,
                      const float* __restrict__ Y,
                      const float* __restrict__ step,
                      const int*   __restrict__ idxp,
                      float*       __restrict__ outX,
                      int K)
{
    char* smem = smem_g;
    const int tid  = threadIdx.x;
    const int w    = tid >> 5;
    const int lane = tid & 31;
    const int g    = lane >> 2;
    const int tg   = lane & 3;
    const int base = blockIdx.x * NT;
    const int kact = *idxp + 1;

    // ---------------- passthrough tiles ----------------
    if (base >= kact) {
        const int col = base + (tid & 63);
        if (col < K) {
            for (int n = (tid >> 6); n < NROW; n += 4)
                outX[(size_t)n * K + col] = X[(size_t)n * K + col];
        }
        return;
    }

    const float s = *step;

    uint32_t* pha16u = (uint32_t*)(smem + PHA);
    uint16_t* rs16   = (uint16_t*)(smem + RS);

    const uint32_t pha_b = smem_u32(smem + PHA);
    const uint32_t xf_b  = smem_u32(smem + XF);
    const uint32_t rs_b  = smem_u32(smem + RS);

    // staging geometry: col = tid&63, k-sixteenth = tid>>6 (16 rows per thread per stage)
    const int scol = tid & 63;
    const int kq   = tid >> 6;
    int gc = base + scol; gc = (gc < K) ? gc : (K - 1);

    // prefetch stage 0 FIRST (latency hides under phi staging)
    float xr[16];
    ldg_stage(X, 0, kq, gc, K, xr);

    // ---------------- stage phi (fp16, native row-major) ----------------
    for (int it = tid; it < MDIM * 128; it += TPB) {
        const int m = it >> 7, kp = it & 127;
        const float2 v = *(const float2*)(phi + m * NROW + 2 * kp);
        pha16u[m * 132 + kp] = pack_h2(v.x, v.y);
    }

    // ================= GEMM A: R(64x64) = phi . Xtile, pipelined 4 stages =================
    const int mbase = 32 * (w & 1);
    const int nbase = 16 * (w >> 1);
    float cA[2][2][4];
    #pragma unroll
    for (int mt = 0; mt < 2; ++mt)
        #pragma unroll
        for (int nt = 0; nt < 2; ++nt)
            #pragma unroll
            for (int q = 0; q < 4; ++q) cA[mt][nt][q] = 0.0f;

    const uint32_t a_row_off = (uint32_t)(lane & 15) * PHA_SB + (uint32_t)((lane >> 4) << 3) * 2;
    const uint32_t b_row     = (uint32_t)(lane & 7);
    const uint32_t b_koff    = (uint32_t)(((lane >> 3) & 1) << 4);

    #pragma unroll 1
    for (int stage = 0; stage < 4; ++stage) {
        const int bufoff = (stage & 1) * XFB;
        sts_stage(smem, bufoff, scol, kq, xr);
        if (stage + 1 < 4)
            ldg_stage(X, stage + 1, kq, gc, K, xr);   // hidden behind sync + MMAs
        __syncthreads();   // single barrier per stage (double-buffered)

        #pragma unroll
        for (int ks = 0; ks < 4; ++ks) {
            const int k0g = stage * 64 + ks * 16;
            const int k0l = ks * 16;
            uint32_t a[2][4];
            #pragma unroll
            for (int mt = 0; mt < 2; ++mt) {
                const uint32_t aoff = (uint32_t)(mbase + 16 * mt) * PHA_SB
                                    + (uint32_t)k0g * 2 + a_row_off;
                LDMX4(a[mt], pha_b + aoff);
            }
            #pragma unroll
            for (int nt = 0; nt < 2; ++nt) {
                const uint32_t roff = (uint32_t)bufoff
                                    + (uint32_t)(nbase + nt * 8 + b_row) * XF_SB
                                    + (uint32_t)k0l * 2 + b_koff;
                uint32_t b[2];
                LDMX2(b, xf_b + roff);
                #pragma unroll
                for (int mt = 0; mt < 2; ++mt)
                    MMA_F16(cA[mt][nt], a[mt], b[0], b[1]);
            }
        }
    }
    // NOTE: no sync needed here. RS aliases buf0; buf0 was last read in stage 2's MMAs,
    // and every warp passed sync(stage=3) after finishing them. Own cA is in-order.

    // ---- epilogue A: r = s*(y - R) -> fp16 -> Rs[n][m] (Y read direct) ----
    #pragma unroll
    for (int mt = 0; mt < 2; ++mt)
        #pragma unroll
        for (int nt = 0; nt < 2; ++nt) {
            const int nloc = nbase + nt * 8 + 2 * tg;
            int col0 = base + nloc; col0 = (col0 < K - 1) ? col0 : (K - 2);
            const int m0 = mbase + 16 * mt + g, m1 = m0 + 8;
            const float2 y0 = *(const float2*)(Y + (size_t)m0 * K + col0);
            const float2 y1 = *(const float2*)(Y + (size_t)m1 * K + col0);
            rs16[nloc * 72 + m0]       = __half_as_ushort(__float2half_rn(s * (y0.x - cA[mt][nt][0])));
            rs16[(nloc + 1) * 72 + m0] = __half_as_ushort(__float2half_rn(s * (y0.y - cA[mt][nt][1])));
            rs16[nloc * 72 + m1]       = __half_as_ushort(__float2half_rn(s * (y1.x - cA[mt][nt][2])));
            rs16[(nloc + 1) * 72 + m1] = __half_as_ushort(__float2half_rn(s * (y1.y - cA[mt][nt][3])));
        }
    __syncthreads();

    // ================= GEMM B: corr(256x64) = phiT . R, K=64, 4 passes of n16 =================
    const int lrow = (lane & 7) + ((lane & 16) >> 1);
    const int lcol = (lane & 8);

    // prefetch pass-0 epilogue X (covered by pass-0 fragment loads + MMAs)
    float2 xe[2][2][2];
    #pragma unroll
    for (int mt = 0; mt < 2; ++mt)
        #pragma unroll
        for (int nt = 0; nt < 2; ++nt) {
            int col0 = base + nt * 8 + 2 * tg; col0 = (col0 < K - 1) ? col0 : (K - 2);
            const int r0 = 32 * w + 16 * mt + g;
            xe[mt][nt][0] = *(const float2*)(X + (size_t)r0 * K + col0);
            xe[mt][nt][1] = *(const float2*)(X + (size_t)(r0 + 8) * K + col0);
        }

    #pragma unroll 1
    for (int pass = 0; pass < 4; ++pass) {
        const int nb = pass * 16;
        float cB[2][2][4];
        #pragma unroll
        for (int mt = 0; mt < 2; ++mt)
            #pragma unroll
            for (int nt = 0; nt < 2; ++nt)
                #pragma unroll
                for (int q = 0; q < 4; ++q) cB[mt][nt][q] = 0.0f;

        #pragma unroll
        for (int ks = 0; ks < 4; ++ks) {
            const int k0 = ks * 16;
            uint32_t at[2][4];
            #pragma unroll
            for (int mt = 0; mt < 2; ++mt) {
                const int m0 = 32 * w + 16 * mt;
                const uint32_t off = (uint32_t)((k0 + lrow) * PHA_SB + (m0 + lcol) * 2);
                LDMX4T(at[mt], pha_b + off);
            }
            #pragma unroll
            for (int nt = 0; nt < 2; ++nt) {
                const uint32_t roff = (uint32_t)(nb + nt * 8 + b_row) * RS_SB
                                    + (uint32_t)k0 * 2 + b_koff;
                uint32_t b[2];
                LDMX2(b, rs_b + roff);
                #pragma unroll
                for (int mt = 0; mt < 2; ++mt)
                    MMA_F16(cB[mt][nt], at[mt], b[0], b[1]);
            }
        }

        // ---- epilogue B: out = thresh(X + corr) using prefetched xe ----
        #pragma unroll
        for (int mt = 0; mt < 2; ++mt) {
            #pragma unroll
            for (int nt = 0; nt < 2; ++nt) {
                const int col0 = base + nb + nt * 8 + 2 * tg;
                const int r0 = 32 * w + 16 * mt + g;
                const int r1 = r0 + 8;
                const float2 x0 = xe[mt][nt][0];
                const float2 x1 = xe[mt][nt][1];
                float u00 = x0.x + cB[mt][nt][0];
                float u01 = x0.y + cB[mt][nt][1];
                float u10 = x1.x + cB[mt][nt][2];
                float u11 = x1.y + cB[mt][nt][3];
                u00 = (fabsf(u00) > 0.1f) ? u00 : 0.0f;
                u01 = (fabsf(u01) > 0.1f) ? u01 : 0.0f;
                u10 = (fabsf(u10) > 0.1f) ? u10 : 0.0f;
                u11 = (fabsf(u11) > 0.1f) ? u11 : 0.0f;
                const bool a0 = (col0 < kact), a1 = (col0 + 1 < kact);
                float2 o0, o1;
                o0.x = a0 ? u00 : x0.x;  o0.y = a1 ? u01 : x0.y;
                o1.x = a0 ? u10 : x1.x;  o1.y = a1 ? u11 : x1.y;
                if (col0 + 1 < K) {
                    *(float2*)(outX + (size_t)r0 * K + col0) = o0;
                    *(float2*)(outX + (size_t)r1 * K + col0) = o1;
                }
            }
        }

        // refill xe for next pass (covered by next pass's fragment loads + MMAs)
        if (pass + 1 < 4) {
            const int nbn = (pass + 1) * 16;
            #pragma unroll
            for (int mt = 0; mt < 2; ++mt)
                #pragma unroll
                for (int nt = 0; nt < 2; ++nt) {
                    int col0 = base + nbn + nt * 8 + 2 * tg;
                    col0 = (col0 < K - 1) ? col0 : (K - 2);
                    const int r0 = 32 * w + 16 * mt + g;
                    xe[mt][nt][0] = *(const float2*)(X + (size_t)r0 * K + col0);
                    xe[mt][nt][1] = *(const float2*)(X + (size_t)(r0 + 8) * K + col0);
                }
        }
    }
}

extern "C" void kernel_launch(void* const* d_in, const int* in_sizes, int n_in,
                              void* d_out, int out_size)
{
    const float* phi  = (const float*)d_in[0];
    const float* X    = (const float*)d_in[1];
    const float* Y    = (const float*)d_in[2];
    const float* step = (const float*)d_in[3];
    const int*   idx  = (const int*)d_in[4];

    const int phiN = in_sizes[0];
    const int XN   = in_sizes[1];
    const int K    = XN / NROW;

    float* outX = (float*)d_out;
    if (out_size == phiN + XN) {
        cudaMemcpyAsync(d_out, phi, (size_t)phiN * sizeof(float),
                        cudaMemcpyDeviceToDevice, 0);
        outX = (float*)d_out + phiN;
    }

    cudaFuncSetAttribute(ista_hmma_kernel,
                         cudaFuncAttributeMaxDynamicSharedMemorySize, SMEM_TOTAL);

    const int grid = (K + NT - 1) / NT;
    ista_hmma_kernel<<<grid, TPB, SMEM_TOTAL>>>(phi, X, Y, step, idx, outX, K);
}